// round 14
// baseline (speedup 1.0000x reference)
#include <cuda_runtime.h>
#include <cuda_fp16.h>
#include <cstdint>

#define B_ROWS  131072
#define IN_DIM  1024
#define H_DIM   256
#define OUT_DIM 256
#define M_TILE  32
#define THREADS 256
#define KCH     32

// byte pitches (conflict-free ldsm): xs 80 (5x16), ws/hs 528 (33x16)
#define XP 80
#define WP 528

#define XS_STAGE (M_TILE * XP)            // 2560
#define WS_STAGE (KCH * WP)               // 16896

#define OFF_BIAS 0
#define OFF_ID   1024
#define OFF_XS   1280
#define OFF_WS   (OFF_XS + 2 * XS_STAGE)           // 6400
#define OFF_HS   (OFF_WS + 2 * WS_STAGE)           // 40192
#define SMEM_TOTAL (OFF_HS + M_TILE * WP)          // 57088  (x4 CTAs + 4KB resv = 232.4KB)

__device__ __half g_W1v12[IN_DIM * H_DIM];
__device__ __half g_W2v12[H_DIM * H_DIM];
__device__ __half g_Wov12[H_DIM * OUT_DIM];

__device__ __forceinline__ uint32_t smem_u32(const void* p) {
    uint32_t a;
    asm("{ .reg .u64 t; cvta.to.shared.u64 t, %1; cvt.u32.u64 %0, t; }" : "=r"(a) : "l"(p));
    return a;
}
__device__ __forceinline__ void cp16(uint32_t dst, const void* src) {
    asm volatile("cp.async.cg.shared.global [%0], [%1], 16;" :: "r"(dst), "l"(src) : "memory");
}
#define CP_COMMIT() asm volatile("cp.async.commit_group;" ::: "memory")
#define CP_WAIT1()  asm volatile("cp.async.wait_group 1;" ::: "memory")

__device__ __forceinline__ void ldsm4(uint32_t* r, uint32_t a) {
    asm volatile("ldmatrix.sync.aligned.m8n8.x4.shared.b16 {%0,%1,%2,%3}, [%4];"
                 : "=r"(r[0]), "=r"(r[1]), "=r"(r[2]), "=r"(r[3]) : "r"(a));
}
__device__ __forceinline__ void ldsm4t(uint32_t* r, uint32_t a) {
    asm volatile("ldmatrix.sync.aligned.m8n8.x4.trans.shared.b16 {%0,%1,%2,%3}, [%4];"
                 : "=r"(r[0]), "=r"(r[1]), "=r"(r[2]), "=r"(r[3]) : "r"(a));
}
__device__ __forceinline__ void mma16(float* c, const uint32_t* a, uint32_t b0, uint32_t b1) {
    asm volatile(
        "mma.sync.aligned.m16n8k16.row.col.f32.f16.f16.f32 "
        "{%0,%1,%2,%3}, {%4,%5,%6,%7}, {%8,%9}, {%0,%1,%2,%3};"
        : "+f"(c[0]), "+f"(c[1]), "+f"(c[2]), "+f"(c[3])
        : "r"(a[0]), "r"(a[1]), "r"(a[2]), "r"(a[3]), "r"(b0), "r"(b1));
}
__device__ __forceinline__ uint32_t pack2(float lo, float hi) {
    __half2 h = __floats2half2_rn(lo, hi);
    return *(uint32_t*)&h;
}
__device__ __forceinline__ float apply_act(float z, int id) {
    if (id == 0) return fmaxf(z, 0.0f);
    if (id == 1) return tanhf(z);
    if (id == 2) return 0.5f * z * (1.0f + erff(z * 0.7071067811865475f));
    return 1.0f / (1.0f + __expf(-z));
}

__global__ void convert_w_v12(const float* __restrict__ W1, const float* __restrict__ W2,
                              const float* __restrict__ Wo) {
    int idx = blockIdx.x * 256 + threadIdx.x;
    if (idx < 262144)       g_W1v12[idx]          = __float2half_rn(W1[idx]);
    else if (idx < 327680)  g_W2v12[idx - 262144] = __float2half_rn(W2[idx - 262144]);
    else if (idx < 393216)  g_Wov12[idx - 327680] = __float2half_rn(Wo[idx - 327680]);
}

extern __shared__ unsigned char smem_raw[];

__global__ void __launch_bounds__(THREADS, 4) het_mlp_v12(
    const float* __restrict__ x,
    const float* __restrict__ b1, const float* __restrict__ b2, const float* __restrict__ bo,
    const int* __restrict__ act1, const int* __restrict__ act2,
    float* __restrict__ out)
{
    const int t    = threadIdx.x;
    const int lane = t & 31;
    const int wid  = t >> 5;            // 0..7
    const int g    = lane >> 2;
    const int tg   = lane & 3;
    const int arow = (wid & 1) * 16;    // 2 warps along M (16 rows each)
    const int wcol = (wid >> 1) * 64;   // 4 warps along N (64 cols each)
    const int row0 = blockIdx.x * M_TILE;
    const uint32_t sm = smem_u32(smem_raw);

    float*         bias_s = (float*)(smem_raw + OFF_BIAS);
    unsigned char* id_s   = smem_raw + OFF_ID;

    const uint32_t lrow = lane & 15, lseg = (lane >> 4) * 16;
    const uint32_t aoff_x = lrow * XP + lseg;
    const uint32_t aoff_h = lrow * WP + lseg;
    const uint32_t boff   = lrow * WP + lseg;

    float c[8][4];                       // warp tile 16x64: 32 accum regs
    auto zero_c = [&]() {
        #pragma unroll
        for (int cb = 0; cb < 8; cb++)
            c[cb][0] = c[cb][1] = c[cb][2] = c[cb][3] = 0.0f;
    };

    // ---- one K=32 chunk; B fragments loaded one-at-a-time to keep regs <= 64 ----
    auto compute_chunk = [&](uint32_t abase, uint32_t wbase) {
        #pragma unroll
        for (int kb = 0; kb < 2; kb++) {
            uint32_t a[4];
            ldsm4(a, abase + kb * 32);
            #pragma unroll
            for (int nb = 0; nb < 4; nb++) {
                uint32_t b[4];
                ldsm4t(b, wbase + kb * (16 * WP) + nb * 32);
                mma16(c[2 * nb],     a, b[0], b[1]);
                mma16(c[2 * nb + 1], a, b[2], b[3]);
            }
        }
    };

    // ---- fills ----
    auto fill_w = [&](int s, const __half* Wh, int kc) {
        #pragma unroll
        for (int j = 0; j < 4; j++) {
            int idx = t + j * THREADS;              // 0..1023
            int r = idx >> 5, seg = idx & 31;
            cp16(sm + OFF_WS + s * WS_STAGE + r * WP + seg * 16,
                 Wh + (size_t)(kc * KCH + r) * 256 + seg * 8);
        }
    };
    // x chunk [32r][32k]: 256 float4, 1 per thread
    const int xf_row = t >> 3, xf_c4 = t & 7;
    auto ldg_x = [&](int kc) -> float4 {
        return *(const float4*)(x + (size_t)(row0 + xf_row) * IN_DIM + kc * KCH + xf_c4 * 4);
    };
    auto sts_x = [&](int s, float4 v) {
        uint2 w; w.x = pack2(v.x, v.y); w.y = pack2(v.z, v.w);
        *(uint2*)(smem_raw + OFF_XS + s * XS_STAGE + xf_row * XP + xf_c4 * 8) = w;
    };
    auto epilogue_h = [&]() {
        #pragma unroll
        for (int cb = 0; cb < 8; cb++) {
            int col = wcol + cb * 8 + 2 * tg;
            float bb0 = bias_s[col], bb1 = bias_s[col + 1];
            int   id0 = id_s[col],   id1 = id_s[col + 1];
            #pragma unroll
            for (int h = 0; h < 2; h++) {
                int row = arow + g + 8 * h;
                float v0 = apply_act(c[cb][2 * h]     + bb0, id0);
                float v1 = apply_act(c[cb][2 * h + 1] + bb1, id1);
                *(uint32_t*)(smem_raw + OFF_HS + row * WP + col * 2) = pack2(v0, v1);
            }
        }
    };

    // ================= Layer 1: 32 chunks of K=32 =================
    zero_c();
    bias_s[t] = b1[t]; id_s[t] = (unsigned char)act1[t];
    sts_x(0, ldg_x(0));
    sts_x(1, ldg_x(1));
    fill_w(0, g_W1v12, 0); CP_COMMIT();
    fill_w(1, g_W1v12, 1); CP_COMMIT();

    for (int i = 0; i < 32; i++) {
        int s = i & 1;
        CP_WAIT1();
        __syncthreads();
        const bool more = (i + 2 < 32);
        float4 xr;
        if (more) xr = ldg_x(i + 2);               // overlap LDG with compute
        compute_chunk(sm + OFF_XS + s * XS_STAGE + arow * XP + aoff_x,
                      sm + OFF_WS + s * WS_STAGE + wcol * 2 + boff);
        __syncthreads();
        if (more) { sts_x(s, xr); fill_w(s, g_W1v12, i + 2); }
        CP_COMMIT();
    }
    fill_w(0, g_W2v12, 0); CP_COMMIT();    // overlap next-layer W with epilogue
    fill_w(1, g_W2v12, 1); CP_COMMIT();
    epilogue_h();
    __syncthreads();
    bias_s[t] = b2[t]; id_s[t] = (unsigned char)act2[t];

    // ================= Layer 2: 8 chunks of K=32 (A = hs) =================
    zero_c();
    for (int i = 0; i < 8; i++) {
        int s = i & 1;
        CP_WAIT1();
        __syncthreads();
        compute_chunk(sm + OFF_HS + arow * WP + i * (KCH * 2) + aoff_h,
                      sm + OFF_WS + s * WS_STAGE + wcol * 2 + boff);
        __syncthreads();
        if (i + 2 < 8) fill_w(s, g_W2v12, i + 2);
        CP_COMMIT();
    }
    fill_w(0, g_Wov12, 0); CP_COMMIT();
    fill_w(1, g_Wov12, 1); CP_COMMIT();
    epilogue_h();                          // overwrite hs with h2 (reads done)
    __syncthreads();
    bias_s[t] = bo[t];

    // ================= Layer 3: 8 chunks of K=32 =================
    zero_c();
    for (int i = 0; i < 8; i++) {
        int s = i & 1;
        CP_WAIT1();
        __syncthreads();
        compute_chunk(sm + OFF_HS + arow * WP + i * (KCH * 2) + aoff_h,
                      sm + OFF_WS + s * WS_STAGE + wcol * 2 + boff);
        __syncthreads();
        if (i + 2 < 8) fill_w(s, g_Wov12, i + 2);
        CP_COMMIT();
    }
    // epilogue -> gmem
    #pragma unroll
    for (int cb = 0; cb < 8; cb++) {
        int col = wcol + cb * 8 + 2 * tg;
        float bb0 = bias_s[col], bb1 = bias_s[col + 1];
        #pragma unroll
        for (int h = 0; h < 2; h++) {
            int row = row0 + arow + g + 8 * h;
            float2 v = make_float2(c[cb][2 * h] + bb0, c[cb][2 * h + 1] + bb1);
            *(float2*)(out + (size_t)row * OUT_DIM + col) = v;
        }
    }
}

extern "C" void kernel_launch(void* const* d_in, const int* in_sizes, int n_in,
                              void* d_out, int out_size) {
    (void)in_sizes; (void)n_in; (void)out_size;
    const float* x  = (const float*)d_in[0];
    const float* W1 = (const float*)d_in[1];
    const float* b1 = (const float*)d_in[2];
    const float* W2 = (const float*)d_in[3];
    const float* b2 = (const float*)d_in[4];
    const float* Wo = (const float*)d_in[5];
    const float* bo = (const float*)d_in[6];
    const int*   a1 = (const int*)d_in[7];
    const int*   a2 = (const int*)d_in[8];

    convert_w_v12<<<1536, 256>>>(W1, W2, Wo);

    cudaFuncSetAttribute(het_mlp_v12, cudaFuncAttributeMaxDynamicSharedMemorySize, SMEM_TOTAL);
    het_mlp_v12<<<B_ROWS / M_TILE, THREADS, SMEM_TOTAL>>>(
        x, b1, b2, bo, a1, a2, (float*)d_out);
}

// round 16
// speedup vs baseline: 1.6990x; 1.6990x over previous
#include <cuda_runtime.h>
#include <cuda_fp16.h>
#include <cstdint>

#define B_ROWS  131072
#define IN_DIM  1024
#define H_DIM   256
#define OUT_DIM 256
#define M_TILE  32
#define THREADS 256
#define KCH     32
#define NSTG    3

// byte pitches (conflict-free ldsm): xs 80 (5x16), ws/hs 528 (33x16)
#define XP 80
#define WP 528

#define XS_STAGE (M_TILE * XP)            // 2560
#define WS_STAGE (KCH * WP)               // 16896

#define OFF_BIAS 0
#define OFF_ID   1024
#define OFF_XS   1280
#define OFF_WS   (OFF_XS + NSTG * XS_STAGE)        // 8960
#define OFF_HS   (OFF_WS + NSTG * WS_STAGE)        // 59648
#define SMEM_TOTAL (OFF_HS + M_TILE * WP)          // 76544  (x3 CTAs = 229.6KB)

__device__ __half g_W1v13[IN_DIM * H_DIM];
__device__ __half g_W2v13[H_DIM * H_DIM];
__device__ __half g_Wov13[H_DIM * OUT_DIM];

__device__ __forceinline__ uint32_t smem_u32(const void* p) {
    uint32_t a;
    asm("{ .reg .u64 t; cvta.to.shared.u64 t, %1; cvt.u32.u64 %0, t; }" : "=r"(a) : "l"(p));
    return a;
}
__device__ __forceinline__ void cp16(uint32_t dst, const void* src) {
    asm volatile("cp.async.cg.shared.global [%0], [%1], 16;" :: "r"(dst), "l"(src) : "memory");
}
#define CP_COMMIT() asm volatile("cp.async.commit_group;" ::: "memory")
#define CP_WAIT1()  asm volatile("cp.async.wait_group 1;" ::: "memory")

__device__ __forceinline__ void ldsm4(uint32_t* r, uint32_t a) {
    asm volatile("ldmatrix.sync.aligned.m8n8.x4.shared.b16 {%0,%1,%2,%3}, [%4];"
                 : "=r"(r[0]), "=r"(r[1]), "=r"(r[2]), "=r"(r[3]) : "r"(a));
}
__device__ __forceinline__ void ldsm4t(uint32_t* r, uint32_t a) {
    asm volatile("ldmatrix.sync.aligned.m8n8.x4.trans.shared.b16 {%0,%1,%2,%3}, [%4];"
                 : "=r"(r[0]), "=r"(r[1]), "=r"(r[2]), "=r"(r[3]) : "r"(a));
}
__device__ __forceinline__ void mma16(float* c, const uint32_t* a, uint32_t b0, uint32_t b1) {
    asm volatile(
        "mma.sync.aligned.m16n8k16.row.col.f32.f16.f16.f32 "
        "{%0,%1,%2,%3}, {%4,%5,%6,%7}, {%8,%9}, {%0,%1,%2,%3};"
        : "+f"(c[0]), "+f"(c[1]), "+f"(c[2]), "+f"(c[3])
        : "r"(a[0]), "r"(a[1]), "r"(a[2]), "r"(a[3]), "r"(b0), "r"(b1));
}
__device__ __forceinline__ uint32_t pack2(float lo, float hi) {
    __half2 h = __floats2half2_rn(lo, hi);
    return *(uint32_t*)&h;
}
__device__ __forceinline__ float apply_act(float z, int id) {
    if (id == 0) return fmaxf(z, 0.0f);
    if (id == 1) return tanhf(z);
    if (id == 2) return 0.5f * z * (1.0f + erff(z * 0.7071067811865475f));
    return 1.0f / (1.0f + __expf(-z));
}

__global__ void convert_w_v13(const float* __restrict__ W1, const float* __restrict__ W2,
                              const float* __restrict__ Wo) {
    int idx = blockIdx.x * 256 + threadIdx.x;
    if (idx < 262144)       g_W1v13[idx]          = __float2half_rn(W1[idx]);
    else if (idx < 327680)  g_W2v13[idx - 262144] = __float2half_rn(W2[idx - 262144]);
    else if (idx < 393216)  g_Wov13[idx - 327680] = __float2half_rn(Wo[idx - 327680]);
}

extern __shared__ unsigned char smem_raw[];

__global__ void __launch_bounds__(THREADS, 3) het_mlp_v13(
    const float* __restrict__ x,
    const float* __restrict__ b1, const float* __restrict__ b2, const float* __restrict__ bo,
    const int* __restrict__ act1, const int* __restrict__ act2,
    float* __restrict__ out)
{
    const int t    = threadIdx.x;
    const int lane = t & 31;
    const int wid  = t >> 5;            // 0..7
    const int g    = lane >> 2;
    const int tg   = lane & 3;
    const int arow = (wid & 1) * 16;    // 2 warps along M (16 rows each)
    const int wcol = (wid >> 1) * 64;   // 4 warps along N (64 cols each)
    const int row0 = blockIdx.x * M_TILE;
    const uint32_t sm = smem_u32(smem_raw);

    float*         bias_s = (float*)(smem_raw + OFF_BIAS);
    unsigned char* id_s   = smem_raw + OFF_ID;

    const uint32_t lrow = lane & 15, lseg = (lane >> 4) * 16;
    const uint32_t aoff_x = lrow * XP + lseg;
    const uint32_t aoff_h = lrow * WP + lseg;
    const uint32_t boff   = lrow * WP + lseg;

    float c[8][4];                       // warp tile 16x64: 32 accum regs
    auto zero_c = [&]() {
        #pragma unroll
        for (int cb = 0; cb < 8; cb++)
            c[cb][0] = c[cb][1] = c[cb][2] = c[cb][3] = 0.0f;
    };

    // ---- one K=32 chunk: batched B-frag loads (ILP), 16 MMA / 10 ldsm ----
    auto compute_chunk = [&](uint32_t abase, uint32_t wbase) {
        #pragma unroll
        for (int kb = 0; kb < 2; kb++) {
            uint32_t a[4], b[4][4];
            ldsm4(a, abase + kb * 32);
            #pragma unroll
            for (int nb = 0; nb < 4; nb++)
                ldsm4t(b[nb], wbase + kb * (16 * WP) + nb * 32);
            #pragma unroll
            for (int nb = 0; nb < 4; nb++) {
                mma16(c[2 * nb],     a, b[nb][0], b[nb][1]);
                mma16(c[2 * nb + 1], a, b[nb][2], b[nb][3]);
            }
        }
    };

    // ---- fills ----
    auto fill_w = [&](int s, const __half* Wh, int kc) {
        #pragma unroll
        for (int j = 0; j < 4; j++) {
            int idx = t + j * THREADS;              // 0..1023
            int r = idx >> 5, seg = idx & 31;
            cp16(sm + OFF_WS + s * WS_STAGE + r * WP + seg * 16,
                 Wh + (size_t)(kc * KCH + r) * 256 + seg * 8);
        }
    };
    const int xf_row = t >> 3, xf_c4 = t & 7;
    auto ldg_x = [&](int kc) -> float4 {
        return *(const float4*)(x + (size_t)(row0 + xf_row) * IN_DIM + kc * KCH + xf_c4 * 4);
    };
    auto sts_x = [&](int s, float4 v) {
        uint2 w; w.x = pack2(v.x, v.y); w.y = pack2(v.z, v.w);
        *(uint2*)(smem_raw + OFF_XS + s * XS_STAGE + xf_row * XP + xf_c4 * 8) = w;
    };
    auto epilogue_h = [&]() {
        #pragma unroll
        for (int cb = 0; cb < 8; cb++) {
            int col = wcol + cb * 8 + 2 * tg;
            float bb0 = bias_s[col], bb1 = bias_s[col + 1];
            int   id0 = id_s[col],   id1 = id_s[col + 1];
            #pragma unroll
            for (int h = 0; h < 2; h++) {
                int row = arow + g + 8 * h;
                float v0 = apply_act(c[cb][2 * h]     + bb0, id0);
                float v1 = apply_act(c[cb][2 * h + 1] + bb1, id1);
                *(uint32_t*)(smem_raw + OFF_HS + row * WP + col * 2) = pack2(v0, v1);
            }
        }
    };

    // ================= Layer 1: 32 chunks, 3-stage ring, 1 sync/iter =========
    zero_c();
    bias_s[t] = b1[t]; id_s[t] = (unsigned char)act1[t];
    sts_x(0, ldg_x(0));
    sts_x(1, ldg_x(1));
    fill_w(0, g_W1v13, 0); CP_COMMIT();
    fill_w(1, g_W1v13, 1); CP_COMMIT();

    for (int i = 0; i < 32; i++) {
        int s = i % NSTG;
        const bool more = (i + 2 < 32);
        float4 xr;
        if (more) xr = ldg_x(i + 2);               // gmem load in flight early
        CP_WAIT1();                                 // stage i W arrived
        __syncthreads();                            // all warps done with stage i-1
        if (more) {
            sts_x((i + 2) % NSTG, xr);              // overwrites stage read at i-1
            fill_w((i + 2) % NSTG, g_W1v13, i + 2);
        }
        CP_COMMIT();                                // exactly one group per iter
        compute_chunk(sm + OFF_XS + s * XS_STAGE + arow * XP + aoff_x,
                      sm + OFF_WS + s * WS_STAGE + wcol * 2 + boff);
    }
    __syncthreads();                       // all computes done; ws free
    fill_w(0, g_W2v13, 0); CP_COMMIT();    // overlap next-layer W with epilogue
    fill_w(1, g_W2v13, 1); CP_COMMIT();
    epilogue_h();
    __syncthreads();
    bias_s[t] = b2[t]; id_s[t] = (unsigned char)act2[t];

    // ================= Layer 2: 8 chunks (A = hs), 1 sync/iter ===============
    zero_c();
    for (int i = 0; i < 8; i++) {
        int s = i % NSTG;
        CP_WAIT1();
        __syncthreads();
        if (i + 2 < 8) fill_w((i + 2) % NSTG, g_W2v13, i + 2);
        CP_COMMIT();
        compute_chunk(sm + OFF_HS + arow * WP + i * (KCH * 2) + aoff_h,
                      sm + OFF_WS + s * WS_STAGE + wcol * 2 + boff);
    }
    __syncthreads();                       // hs reads + ws reads done
    fill_w(0, g_Wov13, 0); CP_COMMIT();
    fill_w(1, g_Wov13, 1); CP_COMMIT();
    epilogue_h();                          // overwrite hs with h2
    __syncthreads();
    bias_s[t] = bo[t];

    // ================= Layer 3: 8 chunks, 1 sync/iter ========================
    zero_c();
    for (int i = 0; i < 8; i++) {
        int s = i % NSTG;
        CP_WAIT1();
        __syncthreads();
        if (i + 2 < 8) fill_w((i + 2) % NSTG, g_Wov13, i + 2);
        CP_COMMIT();
        compute_chunk(sm + OFF_HS + arow * WP + i * (KCH * 2) + aoff_h,
                      sm + OFF_WS + s * WS_STAGE + wcol * 2 + boff);
    }
    // epilogue -> gmem
    #pragma unroll
    for (int cb = 0; cb < 8; cb++) {
        int col = wcol + cb * 8 + 2 * tg;
        float bb0 = bias_s[col], bb1 = bias_s[col + 1];
        #pragma unroll
        for (int h = 0; h < 2; h++) {
            int row = row0 + arow + g + 8 * h;
            float2 v = make_float2(c[cb][2 * h] + bb0, c[cb][2 * h + 1] + bb1);
            *(float2*)(out + (size_t)row * OUT_DIM + col) = v;
        }
    }
}

extern "C" void kernel_launch(void* const* d_in, const int* in_sizes, int n_in,
                              void* d_out, int out_size) {
    (void)in_sizes; (void)n_in; (void)out_size;
    const float* x  = (const float*)d_in[0];
    const float* W1 = (const float*)d_in[1];
    const float* b1 = (const float*)d_in[2];
    const float* W2 = (const float*)d_in[3];
    const float* b2 = (const float*)d_in[4];
    const float* Wo = (const float*)d_in[5];
    const float* bo = (const float*)d_in[6];
    const int*   a1 = (const int*)d_in[7];
    const int*   a2 = (const int*)d_in[8];

    convert_w_v13<<<1536, 256>>>(W1, W2, Wo);

    cudaFuncSetAttribute(het_mlp_v13, cudaFuncAttributeMaxDynamicSharedMemorySize, SMEM_TOTAL);
    het_mlp_v13<<<B_ROWS / M_TILE, THREADS, SMEM_TOTAL>>>(
        x, b1, b2, bo, a1, a2, (float*)d_out);
}